// round 7
// baseline (speedup 1.0000x reference)
#include <cuda_runtime.h>
#include <cuda_bf16.h>
#include <cstdint>
#include <cstddef>

#define D 128
#define NMAX 100032
#define EMAX 800000

// ---------------- scratch (device globals; no allocation allowed) ----------------
__device__ __align__(128) float g_degO[NMAX];
__device__ __align__(128) float g_degI[NMAX];
__device__ __align__(128) int   g_cntO[NMAX];
__device__ __align__(128) int   g_cntI[NMAX];
__device__ __align__(128) int   g_scan[NMAX];
__device__ __align__(128) int   g_bsum[512];
__device__ __align__(128) int   g_off[NMAX + 1];
__device__ __align__(128) int   g_cur[NMAX];
__device__ __align__(128) int   g_csrc[EMAX];
__device__ __align__(128) float g_agg[(size_t)NMAX * D];
__device__ __align__(128) float g_h[(size_t)NMAX * D];
__device__ __align__(128) int   g_edges[2 * EMAX];
__device__ int g_is64;

// ---------------- dtype probe + edge normalization ----------------
__global__ void k_detect(const void* __restrict__ ei, int n) {
    const long long* e64 = (const long long*)ei;
    int ok = 1;
    for (int i = 0; i < 16; i++) {
        long long v = e64[i];
        if (v < 0 || v >= (long long)n) ok = 0;
    }
    g_is64 = ok;
}
__global__ void k_convert(const void* __restrict__ ei, int E) {
    int i = blockIdx.x * blockDim.x + threadIdx.x;
    if (i >= 2 * E) return;
    g_edges[i] = g_is64 ? (int)((const long long*)ei)[i] : ((const int*)ei)[i];
}

// ---------------- degrees ----------------
__global__ void k_zero_cnt(int n) {
    int i = blockIdx.x * blockDim.x + threadIdx.x;
    if (i < n) { g_cntO[i] = 0; g_cntI[i] = 0; }
}
__global__ void k_count_deg(int E) {
    int e = blockIdx.x * blockDim.x + threadIdx.x;
    if (e >= E) return;
    atomicAdd(&g_cntO[g_edges[e]], 1);
    atomicAdd(&g_cntI[g_edges[E + e]], 1);
}
__global__ void k_finalize_deg(int n) {
    int i = blockIdx.x * blockDim.x + threadIdx.x;
    if (i >= n) return;
    g_degO[i] = rsqrtf((float)max(g_cntO[i], 1));
    g_degI[i] = rsqrtf((float)max(g_cntI[i], 1));
}

// ---------------- CSR scan + bucket ----------------
__global__ void k_scan1(int n) {
    __shared__ int s[256];
    int i = blockIdx.x * 256 + threadIdx.x;
    s[threadIdx.x] = (i < n) ? g_cntI[i] : 0;
    __syncthreads();
#pragma unroll
    for (int off = 1; off < 256; off <<= 1) {
        int t = (threadIdx.x >= off) ? s[threadIdx.x - off] : 0;
        __syncthreads();
        s[threadIdx.x] += t;
        __syncthreads();
    }
    if (i < n) g_scan[i] = s[threadIdx.x];
    if (threadIdx.x == 255) g_bsum[blockIdx.x] = s[255];
}
__global__ void k_scan2(int nb) {
    __shared__ int s[512];
    int t = threadIdx.x;
    s[t] = (t < nb) ? g_bsum[t] : 0;
    __syncthreads();
#pragma unroll
    for (int off = 1; off < 512; off <<= 1) {
        int v = (t >= off) ? s[t - off] : 0;
        __syncthreads();
        s[t] += v;
        __syncthreads();
    }
    if (t < nb) g_bsum[t] = (t == 0) ? 0 : s[t - 1];
}
__global__ void k_scan3(int n, int E) {
    int i = blockIdx.x * 256 + threadIdx.x;
    if (i < n) {
        int off = g_bsum[blockIdx.x] + g_scan[i] - g_cntI[i];
        g_off[i] = off;
        g_cur[i] = off;
    }
    if (i == 0) g_off[n] = E;
}
__global__ void k_bucket(int E) {
    int e = blockIdx.x * blockDim.x + threadIdx.x;
    if (e >= E) return;
    int pos = atomicAdd(&g_cur[g_edges[E + e]], 1);
    g_csrc[pos] = g_edges[e];
}

// ---------------- gather: agg[v] = sum_{(u->v)} src[u] * invdegO[u] ----------------
template <bool FROM_H>
__global__ void k_gather(const float* __restrict__ xin, int n) {
    int v = blockIdx.x * (blockDim.x >> 5) + (threadIdx.x >> 5);
    if (v >= n) return;
    int lane = threadIdx.x & 31;
    const float* src = FROM_H ? g_h : xin;
    int p = g_off[v];
    int end = g_off[v + 1];
    float4 acc0 = make_float4(0.f, 0.f, 0.f, 0.f);
    float4 acc1 = make_float4(0.f, 0.f, 0.f, 0.f);
    for (; p + 1 < end; p += 2) {
        int u0 = g_csrc[p], u1 = g_csrc[p + 1];
        float s0 = g_degO[u0], s1 = g_degO[u1];
        float4 a = reinterpret_cast<const float4*>(src + (size_t)u0 * D)[lane];
        float4 b = reinterpret_cast<const float4*>(src + (size_t)u1 * D)[lane];
        acc0.x += a.x * s0; acc0.y += a.y * s0; acc0.z += a.z * s0; acc0.w += a.w * s0;
        acc1.x += b.x * s1; acc1.y += b.y * s1; acc1.z += b.z * s1; acc1.w += b.w * s1;
    }
    if (p < end) {
        int u0 = g_csrc[p];
        float s0 = g_degO[u0];
        float4 a = reinterpret_cast<const float4*>(src + (size_t)u0 * D)[lane];
        acc0.x += a.x * s0; acc0.y += a.y * s0; acc0.z += a.z * s0; acc0.w += a.w * s0;
    }
    acc0.x += acc1.x; acc0.y += acc1.y; acc0.z += acc1.z; acc0.w += acc1.w;
    reinterpret_cast<float4*>(g_agg + (size_t)v * D)[lane] = acc0;
}

// ================= bf16 split-3 MMA GEMM (portable mma.sync, no tcgen05) =========
// out[i][j] = act( (sum_k agg[i][k]*W[j][k] + b[j]) * invdegI[i] [+ x[i][j]] )
// A = agg tile [128m x 128k] row-major; B = W [128n x 128k] (k-major = mma col-major B)
// split: v = hi + lo (bf16 each); acc += Ah*Bh + Al*Bh + Ah*Bl   (fp32 accumulate)
// smem rows padded to 136 bf16 (68 u32) -> fragment LDS conflict-free.

#define PITCH 68   // u32 per row (136 bf16)

__device__ __forceinline__ void mma_bf16(float* d, const uint32_t* a, const uint32_t* b) {
    asm volatile(
        "mma.sync.aligned.m16n8k16.row.col.f32.bf16.bf16.f32 "
        "{%0,%1,%2,%3}, {%4,%5,%6,%7}, {%8,%9}, {%0,%1,%2,%3};"
        : "+f"(d[0]), "+f"(d[1]), "+f"(d[2]), "+f"(d[3])
        : "r"(a[0]), "r"(a[1]), "r"(a[2]), "r"(a[3]), "r"(b[0]), "r"(b[1]));
}

__device__ __forceinline__ void split2(float x, float y, uint32_t& hi, float& lx, float& ly) {
    __nv_bfloat162 h = __float22bfloat162_rn(make_float2(x, y));
    hi = *reinterpret_cast<uint32_t*>(&h);
    lx = x - __bfloat162float(h.x);
    ly = y - __bfloat162float(h.y);
}

template <bool LAYER1>
__global__ __launch_bounds__(256, 1)
void k_gemm_mma(const float* __restrict__ W, const float* __restrict__ bias,
                const float* __restrict__ xres, float* __restrict__ outp, int n) {
    extern __shared__ uint32_t sm[];
    uint32_t* Ahi = sm;
    uint32_t* Alo = sm + 128 * PITCH;
    uint32_t* Whi = sm + 2 * 128 * PITCH;
    uint32_t* Wlo = sm + 3 * 128 * PITCH;

    const int tid = threadIdx.x;
    const int warp = tid >> 5;
    const int lane = tid & 31;
    const int g = lane >> 2;     // 0..7
    const int t = lane & 3;      // 0..3
    const int rowBase = blockIdx.x * 128;

    // ---- load + split A (agg) and W into smem ----
    for (int idx = tid; idx < 4096; idx += 256) {
        int r = idx >> 5, c4 = idx & 31;      // row, float4-col
        int grow = rowBase + r;
        float4 v = make_float4(0.f, 0.f, 0.f, 0.f);
        if (grow < n) v = reinterpret_cast<const float4*>(g_agg + (size_t)grow * D)[c4];
        uint32_t h0, h1; float lx, ly, lz, lw;
        split2(v.x, v.y, h0, lx, ly);
        split2(v.z, v.w, h1, lz, lw);
        Ahi[r * PITCH + c4 * 2]     = h0;
        Ahi[r * PITCH + c4 * 2 + 1] = h1;
        __nv_bfloat162 l0 = __float22bfloat162_rn(make_float2(lx, ly));
        __nv_bfloat162 l1 = __float22bfloat162_rn(make_float2(lz, lw));
        Alo[r * PITCH + c4 * 2]     = *reinterpret_cast<uint32_t*>(&l0);
        Alo[r * PITCH + c4 * 2 + 1] = *reinterpret_cast<uint32_t*>(&l1);
    }
    for (int idx = tid; idx < 4096; idx += 256) {
        int r = idx >> 5, c4 = idx & 31;
        float4 v = reinterpret_cast<const float4*>(W + (size_t)r * D)[c4];
        uint32_t h0, h1; float lx, ly, lz, lw;
        split2(v.x, v.y, h0, lx, ly);
        split2(v.z, v.w, h1, lz, lw);
        Whi[r * PITCH + c4 * 2]     = h0;
        Whi[r * PITCH + c4 * 2 + 1] = h1;
        __nv_bfloat162 l0 = __float22bfloat162_rn(make_float2(lx, ly));
        __nv_bfloat162 l1 = __float22bfloat162_rn(make_float2(lz, lw));
        Wlo[r * PITCH + c4 * 2]     = *reinterpret_cast<uint32_t*>(&l0);
        Wlo[r * PITCH + c4 * 2 + 1] = *reinterpret_cast<uint32_t*>(&l1);
    }
    __syncthreads();

    // ---- compute: warp owns cols [warp*16, warp*16+16) (2 n-tiles), all 128 rows ----
    float acc[8][2][4];
#pragma unroll
    for (int mt = 0; mt < 8; mt++)
#pragma unroll
        for (int nt = 0; nt < 2; nt++)
#pragma unroll
            for (int q = 0; q < 4; q++) acc[mt][nt][q] = 0.f;

#pragma unroll
    for (int kt = 0; kt < 8; kt++) {
        const int kb = kt * 8;  // u32 offset for this k-tile (16 bf16)
        uint32_t bh[2][2], bl[2][2];
#pragma unroll
        for (int nt = 0; nt < 2; nt++) {
            int wrow = warp * 16 + nt * 8 + g;
            bh[nt][0] = Whi[wrow * PITCH + kb + t];
            bh[nt][1] = Whi[wrow * PITCH + kb + t + 4];
            bl[nt][0] = Wlo[wrow * PITCH + kb + t];
            bl[nt][1] = Wlo[wrow * PITCH + kb + t + 4];
        }
#pragma unroll
        for (int mt = 0; mt < 8; mt++) {
            int ar0 = (mt * 16 + g) * PITCH + kb + t;
            int ar1 = (mt * 16 + g + 8) * PITCH + kb + t;
            uint32_t ah[4], al[4];
            ah[0] = Ahi[ar0]; ah[1] = Ahi[ar1]; ah[2] = Ahi[ar0 + 4]; ah[3] = Ahi[ar1 + 4];
            al[0] = Alo[ar0]; al[1] = Alo[ar1]; al[2] = Alo[ar0 + 4]; al[3] = Alo[ar1 + 4];
#pragma unroll
            for (int nt = 0; nt < 2; nt++) {
                mma_bf16(acc[mt][nt], ah, bh[nt]);   // hi*hi
                mma_bf16(acc[mt][nt], al, bh[nt]);   // lo*hi
                mma_bf16(acc[mt][nt], ah, bl[nt]);   // hi*lo
            }
        }
    }

    // ---- epilogue ----
    float* out = LAYER1 ? g_h : outp;
#pragma unroll
    for (int nt = 0; nt < 2; nt++) {
        int col = warp * 16 + nt * 8 + 2 * t;
        float2 b2 = *reinterpret_cast<const float2*>(bias + col);
#pragma unroll
        for (int mt = 0; mt < 8; mt++) {
            int r0 = rowBase + mt * 16 + g;
            int r1 = r0 + 8;
            if (r0 < n) {
                float inv = g_degI[r0];
                float o0 = (acc[mt][nt][0] + b2.x) * inv;
                float o1 = (acc[mt][nt][1] + b2.y) * inv;
                if (LAYER1) {
                    float2 x2 = *reinterpret_cast<const float2*>(xres + (size_t)r0 * D + col);
                    o0 = fmaxf(o0 + x2.x, 0.f);
                    o1 = fmaxf(o1 + x2.y, 0.f);
                }
                *reinterpret_cast<float2*>(out + (size_t)r0 * D + col) = make_float2(o0, o1);
            }
            if (r1 < n) {
                float inv = g_degI[r1];
                float o0 = (acc[mt][nt][2] + b2.x) * inv;
                float o1 = (acc[mt][nt][3] + b2.y) * inv;
                if (LAYER1) {
                    float2 x2 = *reinterpret_cast<const float2*>(xres + (size_t)r1 * D + col);
                    o0 = fmaxf(o0 + x2.x, 0.f);
                    o1 = fmaxf(o1 + x2.y, 0.f);
                }
                *reinterpret_cast<float2*>(out + (size_t)r1 * D + col) = make_float2(o0, o1);
            }
        }
    }
}

#define SMEM_MMA (4 * 128 * PITCH * 4)   // 139264 bytes

// ---------------- launch ----------------
extern "C" void kernel_launch(void* const* d_in, const int* in_sizes, int n_in,
                              void* d_out, int out_size) {
    const float* x  = (const float*)d_in[0];
    const void*  ei = d_in[1];
    const float* W1 = (const float*)d_in[2];
    const float* b1 = (const float*)d_in[3];
    const float* W2 = (const float*)d_in[4];
    const float* b2 = (const float*)d_in[5];
    float* out      = (float*)d_out;

    const int n = in_sizes[0] / D;   // 100000
    const int E = in_sizes[1] / 2;   // 800000

    const int CB = (E + 255) / 256;
    const int FB = (n + 255) / 256;
    const int NB = (n + 255) / 256;
    const int GAB = (n + 7) / 8;
    const int GB = (n + 127) / 128;

    cudaFuncSetAttribute(k_gemm_mma<true>,  cudaFuncAttributeMaxDynamicSharedMemorySize, SMEM_MMA);
    cudaFuncSetAttribute(k_gemm_mma<false>, cudaFuncAttributeMaxDynamicSharedMemorySize, SMEM_MMA);

    // prep
    k_detect<<<1, 1>>>(ei, n);
    k_convert<<<(2 * E + 255) / 256, 256>>>(ei, E);
    k_zero_cnt<<<FB, 256>>>(n);
    k_count_deg<<<CB, 256>>>(E);
    k_finalize_deg<<<FB, 256>>>(n);
    k_scan1<<<NB, 256>>>(n);
    k_scan2<<<1, 512>>>(NB);
    k_scan3<<<NB, 256>>>(n, E);
    k_bucket<<<CB, 256>>>(E);

    // layer 1: gather -> agg; h = relu((agg@W1^T + b1)*invI + x)
    k_gather<false><<<GAB, 256>>>(x, n);
    k_gemm_mma<true><<<GB, 256, SMEM_MMA>>>(W1, b1, x, nullptr, n);

    // layer 2: gather -> agg; out = (agg@W2^T + b2)*invI
    k_gather<true><<<GAB, 256>>>(nullptr, n);
    k_gemm_mma<false><<<GB, 256, SMEM_MMA>>>(W2, b2, nullptr, out, n);
}

// round 8
// speedup vs baseline: 1.5759x; 1.5759x over previous
#include <cuda_runtime.h>
#include <cuda_bf16.h>
#include <cstdint>
#include <cstddef>

#define D 128
#define NMAX 100096   // multiple of 128
#define EMAX 800000
#define PITCH 68      // u32 per smem row (136 bf16), conflict-free fragments

// ---------------- scratch (device globals; no allocation allowed) ----------------
__device__ __align__(128) float    g_degO[NMAX];
__device__ __align__(128) float    g_degI[NMAX];
__device__ __align__(128) int      g_cntO[NMAX];
__device__ __align__(128) int      g_cntI[NMAX];
__device__ __align__(128) int      g_scan[NMAX];
__device__ __align__(128) int      g_bsum[512];
__device__ __align__(128) int      g_off[NMAX + 1];
__device__ __align__(128) int      g_cur[NMAX];
__device__ __align__(128) int      g_csrc[EMAX];
__device__ __align__(128) uint32_t g_ahi[(size_t)NMAX * 64];  // agg hi, packed bf16x2
__device__ __align__(128) uint32_t g_alo[(size_t)NMAX * 64];  // agg lo
__device__ __align__(128) float    g_h[(size_t)NMAX * D];     // layer-1 output (fp32)
__device__ __align__(128) uint32_t g_w1hi[D * 64];
__device__ __align__(128) uint32_t g_w1lo[D * 64];
__device__ __align__(128) uint32_t g_w2hi[D * 64];
__device__ __align__(128) uint32_t g_w2lo[D * 64];
__device__ __align__(128) int      g_edges[2 * EMAX];
__device__ int g_is64;

// ---------------- dtype probe + edge normalization ----------------
__global__ void k_detect(const void* __restrict__ ei, int n) {
    const long long* e64 = (const long long*)ei;
    int ok = 1;
    for (int i = 0; i < 16; i++) {
        long long v = e64[i];
        if (v < 0 || v >= (long long)n) ok = 0;
    }
    g_is64 = ok;
}
__global__ void k_convert(const void* __restrict__ ei, int E) {
    int i = blockIdx.x * blockDim.x + threadIdx.x;
    if (i >= 2 * E) return;
    g_edges[i] = g_is64 ? (int)((const long long*)ei)[i] : ((const int*)ei)[i];
}

// ---------------- degrees ----------------
__global__ void k_zero_cnt(int n) {
    int i = blockIdx.x * blockDim.x + threadIdx.x;
    if (i < n) { g_cntO[i] = 0; g_cntI[i] = 0; }
}
__global__ void k_count_deg(int E) {
    int e = blockIdx.x * blockDim.x + threadIdx.x;
    if (e >= E) return;
    atomicAdd(&g_cntO[g_edges[e]], 1);
    atomicAdd(&g_cntI[g_edges[E + e]], 1);
}
__global__ void k_finalize_deg(int n) {
    int i = blockIdx.x * blockDim.x + threadIdx.x;
    if (i >= n) return;
    g_degO[i] = rsqrtf((float)max(g_cntO[i], 1));
    g_degI[i] = rsqrtf((float)max(g_cntI[i], 1));
}

// ---------------- W split prep: W[j][k] fp32 -> packed bf16 hi/lo ----------------
__global__ void k_splitw(const float* __restrict__ W1, const float* __restrict__ W2) {
    int i = blockIdx.x * blockDim.x + threadIdx.x;   // 0 .. 2*128*64-1 (u32 granule)
    if (i >= 2 * D * 64) return;
    int which = i >= D * 64;
    int idx = which ? i - D * 64 : i;
    const float* W = which ? W2 : W1;
    float2 v = reinterpret_cast<const float2*>(W)[idx];
    __nv_bfloat162 h = __float22bfloat162_rn(make_float2(v.x, v.y));
    float lx = v.x - __bfloat162float(h.x);
    float ly = v.y - __bfloat162float(h.y);
    __nv_bfloat162 l = __float22bfloat162_rn(make_float2(lx, ly));
    uint32_t* hi = which ? g_w2hi : g_w1hi;
    uint32_t* lo = which ? g_w2lo : g_w1lo;
    hi[idx] = *reinterpret_cast<uint32_t*>(&h);
    lo[idx] = *reinterpret_cast<uint32_t*>(&l);
}

// ---------------- CSR scan + bucket ----------------
__global__ void k_scan1(int n) {
    __shared__ int s[256];
    int i = blockIdx.x * 256 + threadIdx.x;
    s[threadIdx.x] = (i < n) ? g_cntI[i] : 0;
    __syncthreads();
#pragma unroll
    for (int off = 1; off < 256; off <<= 1) {
        int t = (threadIdx.x >= off) ? s[threadIdx.x - off] : 0;
        __syncthreads();
        s[threadIdx.x] += t;
        __syncthreads();
    }
    if (i < n) g_scan[i] = s[threadIdx.x];
    if (threadIdx.x == 255) g_bsum[blockIdx.x] = s[255];
}
__global__ void k_scan2(int nb) {
    __shared__ int s[512];
    int t = threadIdx.x;
    s[t] = (t < nb) ? g_bsum[t] : 0;
    __syncthreads();
#pragma unroll
    for (int off = 1; off < 512; off <<= 1) {
        int v = (t >= off) ? s[t - off] : 0;
        __syncthreads();
        s[t] += v;
        __syncthreads();
    }
    if (t < nb) g_bsum[t] = (t == 0) ? 0 : s[t - 1];
}
__global__ void k_scan3(int n, int E) {
    int i = blockIdx.x * 256 + threadIdx.x;
    if (i < n) {
        int off = g_bsum[blockIdx.x] + g_scan[i] - g_cntI[i];
        g_off[i] = off;
        g_cur[i] = off;
    }
    if (i == 0) g_off[n] = E;
}
__global__ void k_bucket(int E) {
    int e = blockIdx.x * blockDim.x + threadIdx.x;
    if (e >= E) return;
    int pos = atomicAdd(&g_cur[g_edges[E + e]], 1);
    g_csrc[pos] = g_edges[e];
}

// ---------------- gather: agg[v] = sum src[u]*invO[u]; writes bf16 hi/lo ----------
template <bool FROM_H>
__global__ void k_gather(const float* __restrict__ xin, int n) {
    int v = blockIdx.x * (blockDim.x >> 5) + (threadIdx.x >> 5);
    if (v >= n) return;
    int lane = threadIdx.x & 31;
    const float* src = FROM_H ? g_h : xin;
    int p = g_off[v];
    int end = g_off[v + 1];
    float4 acc0 = make_float4(0.f, 0.f, 0.f, 0.f);
    float4 acc1 = make_float4(0.f, 0.f, 0.f, 0.f);
    for (; p + 1 < end; p += 2) {
        int u0 = g_csrc[p], u1 = g_csrc[p + 1];
        float s0 = g_degO[u0], s1 = g_degO[u1];
        float4 a = reinterpret_cast<const float4*>(src + (size_t)u0 * D)[lane];
        float4 b = reinterpret_cast<const float4*>(src + (size_t)u1 * D)[lane];
        acc0.x += a.x * s0; acc0.y += a.y * s0; acc0.z += a.z * s0; acc0.w += a.w * s0;
        acc1.x += b.x * s1; acc1.y += b.y * s1; acc1.z += b.z * s1; acc1.w += b.w * s1;
    }
    if (p < end) {
        int u0 = g_csrc[p];
        float s0 = g_degO[u0];
        float4 a = reinterpret_cast<const float4*>(src + (size_t)u0 * D)[lane];
        acc0.x += a.x * s0; acc0.y += a.y * s0; acc0.z += a.z * s0; acc0.w += a.w * s0;
    }
    acc0.x += acc1.x; acc0.y += acc1.y; acc0.z += acc1.z; acc0.w += acc1.w;

    __nv_bfloat162 h0 = __float22bfloat162_rn(make_float2(acc0.x, acc0.y));
    __nv_bfloat162 h1 = __float22bfloat162_rn(make_float2(acc0.z, acc0.w));
    __nv_bfloat162 l0 = __float22bfloat162_rn(make_float2(acc0.x - __bfloat162float(h0.x),
                                                          acc0.y - __bfloat162float(h0.y)));
    __nv_bfloat162 l1 = __float22bfloat162_rn(make_float2(acc0.z - __bfloat162float(h1.x),
                                                          acc0.w - __bfloat162float(h1.y)));
    uint2 hv = make_uint2(*reinterpret_cast<uint32_t*>(&h0), *reinterpret_cast<uint32_t*>(&h1));
    uint2 lv = make_uint2(*reinterpret_cast<uint32_t*>(&l0), *reinterpret_cast<uint32_t*>(&l1));
    reinterpret_cast<uint2*>(g_ahi + (size_t)v * 64)[lane] = hv;
    reinterpret_cast<uint2*>(g_alo + (size_t)v * 64)[lane] = lv;
}

// ================= bf16 split-3 MMA GEMM, 512 threads =================
// warp w: n-pair p=w&7 -> cols [p*16, p*16+16); m-half = w>>3 -> rows [mh*64, +64)
__device__ __forceinline__ void mma_bf16(float* d, const uint32_t* a, const uint32_t* b) {
    asm volatile(
        "mma.sync.aligned.m16n8k16.row.col.f32.bf16.bf16.f32 "
        "{%0,%1,%2,%3}, {%4,%5,%6,%7}, {%8,%9}, {%0,%1,%2,%3};"
        : "+f"(d[0]), "+f"(d[1]), "+f"(d[2]), "+f"(d[3])
        : "r"(a[0]), "r"(a[1]), "r"(a[2]), "r"(a[3]), "r"(b[0]), "r"(b[1]));
}

#define SMEM_MMA (4 * 128 * PITCH * 4)   // Ahi, Alo, Whi, Wlo: 139264 B

template <bool LAYER1>
__global__ __launch_bounds__(512, 1)
void k_gemm_mma(const float* __restrict__ bias,
                const float* __restrict__ xres, float* __restrict__ outp, int n) {
    extern __shared__ uint32_t sm[];
    uint32_t* Ahi = sm;
    uint32_t* Alo = sm + 128 * PITCH;
    uint32_t* Whi = sm + 2 * 128 * PITCH;
    uint32_t* Wlo = sm + 3 * 128 * PITCH;

    const uint32_t* whi = LAYER1 ? g_w1hi : g_w1lo == nullptr ? g_w1hi : g_w2hi; // (never null; keep simple)
    const uint32_t* wlo = LAYER1 ? g_w1lo : g_w2lo;
    const uint32_t* whi2 = LAYER1 ? g_w1hi : g_w2hi;

    const int tid = threadIdx.x;
    const int warp = tid >> 5;
    const int lane = tid & 31;
    const int g = lane >> 2;
    const int t = lane & 3;
    const int rowBase = blockIdx.x * 128;
    const int p = warp & 7;        // n-pair
    const int mh = warp >> 3;      // m-half

    // ---- fill smem: straight uint4 copies (splits precomputed) ----
#pragma unroll
    for (int it = 0; it < 4; it++) {
        int idx = tid + it * 512;            // 0..2047
        int r = idx >> 4, c = idx & 15;      // row, uint4-col
        int grow = rowBase + r;
        uint4 vh = make_uint4(0u, 0u, 0u, 0u), vl = vh;
        if (grow < n) {
            vh = reinterpret_cast<const uint4*>(g_ahi + (size_t)grow * 64)[c];
            vl = reinterpret_cast<const uint4*>(g_alo + (size_t)grow * 64)[c];
        }
        *reinterpret_cast<uint4*>(Ahi + r * PITCH + c * 4) = vh;
        *reinterpret_cast<uint4*>(Alo + r * PITCH + c * 4) = vl;
    }
#pragma unroll
    for (int it = 0; it < 2; it++) {
        int idx = tid + it * 512;            // 0..1023? need 2048 total for W hi+lo
        int r = idx >> 3;                    // 0..127 (8 uint4 = wait)
        // W: 128 rows x 16 uint4 = 2048 uint4 for hi+lo combined -> handle both here
        int c = idx & 7;                     // 8 uint4 per half-row
        // map idx 0..1023 -> (r, c) over 128x8; do hi with c, lo with c (two stores)
        *reinterpret_cast<uint4*>(Whi + r * PITCH + c * 4) =
            reinterpret_cast<const uint4*>(whi2 + r * 64)[c];
        *reinterpret_cast<uint4*>(Whi + r * PITCH + (c + 8) * 4) =
            reinterpret_cast<const uint4*>(whi2 + r * 64)[c + 8];
        *reinterpret_cast<uint4*>(Wlo + r * PITCH + c * 4) =
            reinterpret_cast<const uint4*>(wlo + r * 64)[c];
        *reinterpret_cast<uint4*>(Wlo + r * PITCH + (c + 8) * 4) =
            reinterpret_cast<const uint4*>(wlo + r * 64)[c + 8];
    }
    __syncthreads();

    // ---- preload B-hi fragments for this warp's 2 n-tiles, all 8 k-tiles ----
    uint32_t bh[8][2][2];
#pragma unroll
    for (int kt = 0; kt < 8; kt++) {
        int kb = kt * 8;
#pragma unroll
        for (int nt = 0; nt < 2; nt++) {
            int wrow = p * 16 + nt * 8 + g;
            bh[kt][nt][0] = Whi[wrow * PITCH + kb + t];
            bh[kt][nt][1] = Whi[wrow * PITCH + kb + t + 4];
        }
    }

    float acc[4][2][4];
#pragma unroll
    for (int mt = 0; mt < 4; mt++)
#pragma unroll
        for (int nt = 0; nt < 2; nt++)
#pragma unroll
            for (int q = 0; q < 4; q++) acc[mt][nt][q] = 0.f;

#pragma unroll
    for (int kt = 0; kt < 8; kt++) {
        const int kb = kt * 8;
        uint32_t bl[2][2];
#pragma unroll
        for (int nt = 0; nt < 2; nt++) {
            int wrow = p * 16 + nt * 8 + g;
            bl[nt][0] = Wlo[wrow * PITCH + kb + t];
            bl[nt][1] = Wlo[wrow * PITCH + kb + t + 4];
        }
#pragma unroll
        for (int mt = 0; mt < 4; mt++) {
            int r0 = (mh * 64 + mt * 16 + g) * PITCH + kb + t;
            int r1 = (mh * 64 + mt * 16 + g + 8) * PITCH + kb + t;
            uint32_t ah[4], al[4];
            ah[0] = Ahi[r0]; ah[1] = Ahi[r1]; ah[2] = Ahi[r0 + 4]; ah[3] = Ahi[r1 + 4];
            al[0] = Alo[r0]; al[1] = Alo[r1]; al[2] = Alo[r0 + 4]; al[3] = Alo[r1 + 4];
#pragma unroll
            for (int nt = 0; nt < 2; nt++) {
                mma_bf16(acc[mt][nt], ah, bh[kt][nt]);   // hi*hi
                mma_bf16(acc[mt][nt], al, bh[kt][nt]);   // lo*hi
                mma_bf16(acc[mt][nt], ah, bl[nt]);       // hi*lo
            }
        }
    }

    // ---- epilogue ----
    float* out = LAYER1 ? g_h : outp;
#pragma unroll
    for (int nt = 0; nt < 2; nt++) {
        int col = p * 16 + nt * 8 + 2 * t;
        float2 b2 = *reinterpret_cast<const float2*>(bias + col);
#pragma unroll
        for (int mt = 0; mt < 4; mt++) {
            int r0 = rowBase + mh * 64 + mt * 16 + g;
            int r1 = r0 + 8;
            if (r0 < n) {
                float inv = g_degI[r0];
                float o0 = (acc[mt][nt][0] + b2.x) * inv;
                float o1 = (acc[mt][nt][1] + b2.y) * inv;
                if (LAYER1) {
                    float2 x2 = *reinterpret_cast<const float2*>(xres + (size_t)r0 * D + col);
                    o0 = fmaxf(o0 + x2.x, 0.f);
                    o1 = fmaxf(o1 + x2.y, 0.f);
                }
                *reinterpret_cast<float2*>(out + (size_t)r0 * D + col) = make_float2(o0, o1);
            }
            if (r1 < n) {
                float inv = g_degI[r1];
                float o0 = (acc[mt][nt][2] + b2.x) * inv;
                float o1 = (acc[mt][nt][3] + b2.y) * inv;
                if (LAYER1) {
                    float2 x2 = *reinterpret_cast<const float2*>(xres + (size_t)r1 * D + col);
                    o0 = fmaxf(o0 + x2.x, 0.f);
                    o1 = fmaxf(o1 + x2.y, 0.f);
                }
                *reinterpret_cast<float2*>(out + (size_t)r1 * D + col) = make_float2(o0, o1);
            }
        }
    }
}

// ---------------- launch ----------------
extern "C" void kernel_launch(void* const* d_in, const int* in_sizes, int n_in,
                              void* d_out, int out_size) {
    const float* x  = (const float*)d_in[0];
    const void*  ei = d_in[1];
    const float* W1 = (const float*)d_in[2];
    const float* b1 = (const float*)d_in[3];
    const float* W2 = (const float*)d_in[4];
    const float* b2 = (const float*)d_in[5];
    float* out      = (float*)d_out;

    const int n = in_sizes[0] / D;   // 100000
    const int E = in_sizes[1] / 2;   // 800000

    const int CB = (E + 255) / 256;
    const int FB = (n + 255) / 256;
    const int NB = (n + 255) / 256;
    const int GAB = (n + 7) / 8;
    const int GB = (n + 127) / 128;

    cudaFuncSetAttribute(k_gemm_mma<true>,  cudaFuncAttributeMaxDynamicSharedMemorySize, SMEM_MMA);
    cudaFuncSetAttribute(k_gemm_mma<false>, cudaFuncAttributeMaxDynamicSharedMemorySize, SMEM_MMA);

    // prep
    k_detect<<<1, 1>>>(ei, n);
    k_convert<<<(2 * E + 255) / 256, 256>>>(ei, E);
    k_zero_cnt<<<FB, 256>>>(n);
    k_splitw<<<(2 * D * 64 + 255) / 256, 256>>>(W1, W2);
    k_count_deg<<<CB, 256>>>(E);
    k_finalize_deg<<<FB, 256>>>(n);
    k_scan1<<<NB, 256>>>(n);
    k_scan2<<<1, 512>>>(NB);
    k_scan3<<<NB, 256>>>(n, E);
    k_bucket<<<CB, 256>>>(E);

    // layer 1: gather -> (ahi, alo); h = relu((agg@W1^T + b1)*invI + x)
    k_gather<false><<<GAB, 256>>>(x, n);
    k_gemm_mma<true><<<GB, 512, SMEM_MMA>>>(b1, x, nullptr, n);

    // layer 2: gather(h) -> (ahi, alo); out = (agg@W2^T + b2)*invI
    k_gather<true><<<GAB, 256>>>(nullptr, n);
    k_gemm_mma<false><<<GB, 512, SMEM_MMA>>>(b2, nullptr, out, n);
}